// round 10
// baseline (speedup 1.0000x reference)
#include <cuda_runtime.h>
#include <cuda_bf16.h>
#include <math.h>

// Problem constants
#define H   1024
#define IW  512          // moe_intermediate_size
#define E   16
#define T   4096         // B*S tokens
#define P   8192         // T * K pairs
#define ISH 1024         // shared intermediate (I * 2)

// ---------------- device scratch (static globals; no runtime allocation) ----
__device__ int   g_count[16];
__device__ int   g_offsets[17];
__device__ int   g_cursor[16];
__device__ int   g_topk_idx[T * 2];
__device__ float g_topk_w[T * 2];
__device__ int   g_pair_token[P];
__device__ int   g_pos_of[T * 2];
// gate|up concatenated per pair row [P][1024]; after silu kernel, cols [0,512) hold act
__device__ float g_gu[(size_t)P * 1024];
// down-projection per pair row [P][1024]
__device__ float g_down[(size_t)P * 1024];
// shared expert gate|up [T][2048]; after silu kernel, cols [0,1024) hold act
__device__ float g_sgu[(size_t)T * 2048];

// ---------------- small kernels -------------------------------------------
__global__ void k_init() {
    int i = threadIdx.x;
    if (i < 16) g_count[i] = 0;
}

// One block (128 threads) per token: 16 router dots, softmax-top2 closed form.
__global__ void k_router(const float* __restrict__ x,
                         const float* __restrict__ rw) {
    int t = blockIdx.x;
    __shared__ float xs[H];
    __shared__ float sc[16];
    int tid = threadIdx.x;
    const float4* xv = (const float4*)(x + (size_t)t * H);
    ((float4*)xs)[tid]       = xv[tid];
    ((float4*)xs)[tid + 128] = xv[tid + 128];
    __syncthreads();

    int e = tid >> 3, lane = tid & 7;
    const float* w = rw + (size_t)e * H;
    float s = 0.f;
    #pragma unroll 4
    for (int h = lane * 4; h < H; h += 32) {
        float4 a = *(const float4*)(xs + h);
        float4 b = *(const float4*)(w + h);
        s += a.x * b.x + a.y * b.y + a.z * b.z + a.w * b.w;
    }
    #pragma unroll
    for (int o = 4; o; o >>= 1) s += __shfl_down_sync(0xffffffffu, s, o, 8);
    if (lane == 0) sc[e] = s;
    __syncthreads();

    if (tid == 0) {
        int i1 = 0; float s1 = sc[0];
        #pragma unroll
        for (int i = 1; i < 16; i++) if (sc[i] > s1) { s1 = sc[i]; i1 = i; }
        int i2 = -1; float s2 = -3.0e38f;
        #pragma unroll
        for (int i = 0; i < 16; i++) if (i != i1 && sc[i] > s2) { s2 = sc[i]; i2 = i; }
        // normalized top-2 softmax weights: softmax denom cancels
        float r  = expf(s2 - s1);
        float w1 = 1.f / (1.f + r);
        float w2 = r / (1.f + r);
        g_topk_idx[t * 2]     = i1;
        g_topk_idx[t * 2 + 1] = i2;
        g_topk_w[t * 2]       = w1;
        g_topk_w[t * 2 + 1]   = w2;
        atomicAdd(&g_count[i1], 1);
        atomicAdd(&g_count[i2], 1);
    }
}

__global__ void k_scan() {
    if (threadIdx.x == 0) {
        int o = 0;
        for (int e = 0; e < 16; e++) { g_offsets[e] = o; o += g_count[e]; }
        g_offsets[16] = o;
    }
    if (threadIdx.x < 16) g_cursor[threadIdx.x] = 0;
}

__global__ void k_scatter() {
    int t = blockIdx.x * blockDim.x + threadIdx.x;
    if (t >= T) return;
    #pragma unroll
    for (int s = 0; s < 2; s++) {
        int e   = g_topk_idx[t * 2 + s];
        int pos = g_offsets[e] + atomicAdd(&g_cursor[e], 1);
        g_pair_token[pos]  = t;
        g_pos_of[t * 2 + s] = pos;
    }
}

// ---------------- tiled SGEMM core: 128x64 tile, BK=16, 256 threads --------
#define BM 128
#define BN 64
#define BK 16

__device__ __forceinline__ void gemm_core(
    const float* __restrict__ A, int lda,
    const int* __restrict__ rowmap, int row_off, int Mrem,
    const float* __restrict__ Bt, int ldb,
    float* __restrict__ Ct, int ldc, int K)
{
    __shared__ float As[BK][BM + 4];
    __shared__ float Bs[BK][BN];
    int tid = threadIdx.x;

    // A loaders: 2 float4 per thread per k-tile
    int ar = tid >> 2;           // 0..63
    int ak = (tid & 3) << 2;     // 0,4,8,12
    bool v0 = ar < Mrem;
    bool v1 = (ar + 64) < Mrem;
    const float* ap0 = A;
    const float* ap1 = A;
    if (v0) { int r = rowmap ? rowmap[row_off + ar]      : (row_off + ar);      ap0 = A + (size_t)r * lda + ak; }
    if (v1) { int r = rowmap ? rowmap[row_off + ar + 64] : (row_off + ar + 64); ap1 = A + (size_t)r * lda + ak; }

    // B loader: 1 float4 per thread per k-tile
    int bk = tid >> 4;           // 0..15
    int bn = (tid & 15) << 2;    // 0..60
    const float* bp = Bt + (size_t)bk * ldb + bn;

    int tn = (tid & 15) << 2;    // n sub-tile
    int tm = (tid >> 4) << 2;    // m sub-tile (rows tm..tm+3, tm+64..tm+67)

    float acc[8][4];
    #pragma unroll
    for (int i = 0; i < 8; i++)
        #pragma unroll
        for (int j = 0; j < 4; j++) acc[i][j] = 0.f;

    const float4 z4 = make_float4(0.f, 0.f, 0.f, 0.f);
    for (int k0 = 0; k0 < K; k0 += BK) {
        float4 a0 = v0 ? *(const float4*)(ap0 + k0) : z4;
        float4 a1 = v1 ? *(const float4*)(ap1 + k0) : z4;
        float4 b  = *(const float4*)bp;
        bp += (size_t)BK * ldb;

        __syncthreads();
        As[ak + 0][ar] = a0.x; As[ak + 1][ar] = a0.y;
        As[ak + 2][ar] = a0.z; As[ak + 3][ar] = a0.w;
        As[ak + 0][ar + 64] = a1.x; As[ak + 1][ar + 64] = a1.y;
        As[ak + 2][ar + 64] = a1.z; As[ak + 3][ar + 64] = a1.w;
        *(float4*)(&Bs[bk][bn]) = b;
        __syncthreads();

        #pragma unroll
        for (int kk = 0; kk < BK; kk++) {
            float4 t0 = *(const float4*)(&As[kk][tm]);
            float4 t1 = *(const float4*)(&As[kk][tm + 64]);
            float4 t2 = *(const float4*)(&Bs[kk][tn]);
            float a[8] = { t0.x, t0.y, t0.z, t0.w, t1.x, t1.y, t1.z, t1.w };
            float bb[4] = { t2.x, t2.y, t2.z, t2.w };
            #pragma unroll
            for (int i = 0; i < 8; i++)
                #pragma unroll
                for (int j = 0; j < 4; j++)
                    acc[i][j] = fmaf(a[i], bb[j], acc[i][j]);
        }
    }

    #pragma unroll
    for (int i = 0; i < 8; i++) {
        int m = (i < 4) ? (tm + i) : (tm + 64 + i - 4);
        if (m < Mrem) {
            float4 r = make_float4(acc[i][0], acc[i][1], acc[i][2], acc[i][3]);
            *(float4*)(Ct + (size_t)m * ldc + tn) = r;
        }
    }
}

// ---------------- GEMM wrappers -------------------------------------------
// Routed gate|up: gathered rows of x, virtual N=1024 (cols<512 -> gate, else up)
__global__ void __launch_bounds__(256)
k_routed_gateup(const float* __restrict__ x,
                const float* __restrict__ wg,
                const float* __restrict__ wu) {
    int e   = blockIdx.z;
    int seg = g_offsets[e];
    int ne  = g_offsets[e + 1] - seg;
    int mt  = blockIdx.y * BM;
    if (mt >= ne) return;
    int nt  = blockIdx.x * BN;
    const float* B = (nt < IW) ? (wg + (size_t)e * H * IW + nt)
                               : (wu + (size_t)e * H * IW + (nt - IW));
    gemm_core(x, H, g_pair_token, seg + mt, ne - mt,
              B, IW,
              g_gu + (size_t)(seg + mt) * 1024 + nt, 1024, H);
}

// In-place SiLU(gate)*up for routed pairs: act lands in cols [0,512)
__global__ void k_silu_routed() {
    int idx = blockIdx.x * blockDim.x + threadIdx.x;
    if (idx >= P * IW) return;
    int p = idx >> 9, i = idx & 511;
    float g = g_gu[(size_t)p * 1024 + i];
    float u = g_gu[(size_t)p * 1024 + 512 + i];
    g_gu[(size_t)p * 1024 + i] = g / (1.f + expf(-g)) * u;
}

// Routed down: act rows (stride 1024, K=512) x Wd_e -> g_down (unscaled)
__global__ void __launch_bounds__(256)
k_routed_down(const float* __restrict__ wd) {
    int e   = blockIdx.z;
    int seg = g_offsets[e];
    int ne  = g_offsets[e + 1] - seg;
    int mt  = blockIdx.y * BM;
    if (mt >= ne) return;
    int nt  = blockIdx.x * BN;
    gemm_core(g_gu, 1024, nullptr, seg + mt, ne - mt,
              wd + (size_t)e * IW * H + nt, H,
              g_down + (size_t)(seg + mt) * 1024 + nt, 1024, IW);
}

// Shared gate|up: x direct, virtual N=2048
__global__ void __launch_bounds__(256)
k_shared_gateup(const float* __restrict__ x,
                const float* __restrict__ sg,
                const float* __restrict__ su) {
    int mt = blockIdx.y * BM;
    int nt = blockIdx.x * BN;
    const float* B = (nt < ISH) ? (sg + nt) : (su + (nt - ISH));
    gemm_core(x, H, nullptr, mt, T - mt,
              B, ISH,
              g_sgu + (size_t)mt * 2048 + nt, 2048, H);
}

__global__ void k_silu_shared() {
    int idx = blockIdx.x * blockDim.x + threadIdx.x;
    if (idx >= T * ISH) return;
    int t = idx >> 10, i = idx & 1023;
    float g = g_sgu[(size_t)t * 2048 + i];
    float u = g_sgu[(size_t)t * 2048 + 1024 + i];
    g_sgu[(size_t)t * 2048 + i] = g / (1.f + expf(-g)) * u;
}

// Shared down: writes the shared-expert contribution straight into out ("=")
__global__ void __launch_bounds__(256)
k_shared_down(const float* __restrict__ sd, float* __restrict__ out) {
    int mt = blockIdx.y * BM;
    int nt = blockIdx.x * BN;
    gemm_core(g_sgu, 2048, nullptr, mt, T - mt,
              sd + nt, H,
              out + (size_t)mt * H + nt, H, ISH);
}

// out += w1*down[p1] + w2*down[p2]  (one thread per element -> deterministic)
__global__ void k_combine(float* __restrict__ out) {
    int idx = blockIdx.x * blockDim.x + threadIdx.x;
    if (idx >= T * H) return;
    int t = idx >> 10, h = idx & 1023;
    float r = out[idx];
    r += g_topk_w[t * 2]     * g_down[(size_t)g_pos_of[t * 2]     * 1024 + h];
    r += g_topk_w[t * 2 + 1] * g_down[(size_t)g_pos_of[t * 2 + 1] * 1024 + h];
    out[idx] = r;
}

// ---------------- launch ---------------------------------------------------
extern "C" void kernel_launch(void* const* d_in, const int* in_sizes, int n_in,
                              void* d_out, int out_size) {
    const float* x  = (const float*)d_in[0];   // [T, H]
    const float* rw = (const float*)d_in[1];   // [E, H]
    const float* wg = (const float*)d_in[2];   // [E, H, I]
    const float* wu = (const float*)d_in[3];   // [E, H, I]
    const float* wd = (const float*)d_in[4];   // [E, I, H]
    const float* sg = (const float*)d_in[5];   // [H, IS]
    const float* su = (const float*)d_in[6];   // [H, IS]
    const float* sd = (const float*)d_in[7];   // [IS, H]
    float* out = (float*)d_out;                // [T, H]

    // routing
    k_init<<<1, 32>>>();
    k_router<<<T, 128>>>(x, rw);
    k_scan<<<1, 32>>>();
    k_scatter<<<16, 256>>>();

    // shared expert (writes out with "=")
    k_shared_gateup<<<dim3(2048 / BN, T / BM, 1), 256>>>(x, sg, su);
    k_silu_shared<<<(T * ISH + 255) / 256, 256>>>();
    k_shared_down<<<dim3(H / BN, T / BM, 1), 256>>>(sd, out);

    // routed experts
    k_routed_gateup<<<dim3(1024 / BN, T / BM, E), 256>>>(x, wg, wu);
    k_silu_routed<<<(P * IW + 255) / 256, 256>>>();
    k_routed_down<<<dim3(H / BN, T / BM, E), 256>>>(wd);

    // final combine
    k_combine<<<(T * H + 255) / 256, 256>>>(out);
}